// round 6
// baseline (speedup 1.0000x reference)
#include <cuda_runtime.h>
#include <cuda_fp16.h>

#define N_NODES 50000
#define DS 127
#define DPAD 128
#define NE 800000
#define EPSF 1e-7f
#define GR 32   // rows per gemm block

// g_h  : h1 = relu(agg1)+x (fp32), written by layer-2 gemm prologue; pad col = 0
// g_z  : gemm output in fp16 (row stride 128 halves); pad col = 0
// g_agg: fp32 atomic accumulation target; pad col garbage, never read
__device__ __align__(16) float  g_h[N_NODES * DPAD];
__device__ __align__(16) __half g_z[N_NODES * DPAD];
__device__ __align__(16) float  g_agg[N_NODES * DPAD];

// smem: W_s[127*128 f32] | h2s[32*128 float2 dup] | b_s[128]  = 98304 B (2 CTAs/SM)
#define H_OFF (DS * DPAD)                    // floats
#define B_OFF (H_OFF + GR * DPAD * 2)
#define SMEM_BYTES ((B_OFF + DPAD) * 4)

__device__ __forceinline__ float warp_sum(float v) {
#pragma unroll
    for (int o = 16; o; o >>= 1) v += __shfl_xor_sync(0xffffffffu, v, o);
    return v;
}

__device__ __forceinline__ void fma2(unsigned long long& acc,
                                     unsigned long long a, unsigned long long b) {
    asm("fma.rn.f32x2 %0, %1, %2, %0;" : "+l"(acc) : "l"(a), "l"(b));
}

extern __shared__ float smem[];

// z = half(h @ W + b); agg zeroed in epilogue.
// layer==0: h rows = x (logmap0(expmap0(x)) == x analytically).
// layer==1: h rows = relu(agg) + x (== h1), also stored to g_h for the final skip.
// 256 threads, 32 rows/block. Thread (cx=tid&31, ry=tid>>5): 4 rows x 4 cols,
// accumulated as f32x2 col-pairs; h duplicated {v,v} in smem for packed broadcast.
__global__ void k_gemm(const float* __restrict__ W, const float* __restrict__ b,
                       const float* __restrict__ x, int layer) {
    float* W_s = smem;
    float* b_s = smem + B_OFF;
    float2* h2s = (float2*)(smem + H_OFF);
    int tid  = threadIdx.x;
    int row0 = blockIdx.x * GR;

    // W (pad col 127 -> 0), coalesced
    for (int i = tid; i < DS * DPAD; i += 256) {
        int k = i >> 7, c = i & 127;
        W_s[i] = (c < DS) ? W[k * DS + c] : 0.f;
    }
    if (tid < DPAD) b_s[tid] = (tid < DS) ? b[tid] : 0.f;

    // h tile (duplicated), pad col -> 0
    {
        int c = tid & 127, rr = tid >> 7;
        for (int r = rr; r < GR; r += 2) {
            int row = row0 + r;
            float v = 0.f;
            if (row < N_NODES) {
                if (c < DS) {
                    v = x[row * DS + c];
                    if (layer) {
                        v += fmaxf(g_agg[row * DPAD + c], 0.f);
                        g_h[row * DPAD + c] = v;
                    }
                } else if (layer) {
                    g_h[row * DPAD + c] = 0.f;   // pad col of h1
                }
            }
            h2s[r * DPAD + c] = make_float2(v, v);
        }
    }
    __syncthreads();

    int cx = tid & 31;
    int ry = tid >> 5;

    unsigned long long acc[4][2];
#pragma unroll
    for (int r = 0; r < 4; r++) { acc[r][0] = 0ull; acc[r][1] = 0ull; }

    const ulonglong2* Wu = (const ulonglong2*)W_s;   // [k*32+cx] = {w0,w1},{w2,w3}
    const ulonglong2* Hu = (const ulonglong2*)h2s;   // [row*64 + k/2] = {vk,vk},{vk1,vk1}

#pragma unroll 4
    for (int k = 0; k < DPAD; k += 2) {              // k=126 pairs with pad k=127 (zeros)
        ulonglong2 wa = Wu[k * 32 + cx];
        ulonglong2 wb = Wu[(k + 1) * 32 + cx];
#pragma unroll
        for (int r = 0; r < 4; r++) {
            ulonglong2 h = Hu[(ry * 4 + r) * 64 + (k >> 1)];  // broadcast
            fma2(acc[r][0], h.x, wa.x);
            fma2(acc[r][1], h.x, wa.y);
            fma2(acc[r][0], h.y, wb.x);
            fma2(acc[r][1], h.y, wb.y);
        }
    }

    float4 bb = ((const float4*)b_s)[cx];
    uint2*  z2 = (uint2*)g_z;     // 8B = 4 halves; 32 per row
    float4* a4 = (float4*)g_agg;
#pragma unroll
    for (int r = 0; r < 4; r++) {
        int row = row0 + ry * 4 + r;
        if (row < N_NODES) {
            float2 p0 = *(float2*)&acc[r][0];
            float2 p1 = *(float2*)&acc[r][1];
            float2 q0 = make_float2(p0.x + bb.x, p0.y + bb.y);
            float2 q1 = make_float2(p1.x + bb.z, p1.y + bb.w);
            __half2 h0 = __float22half2_rn(q0);
            __half2 h1 = __float22half2_rn(q1);
            uint2 o;
            o.x = *(unsigned*)&h0;
            o.y = *(unsigned*)&h1;
            z2[row * 32 + cx] = o;
            a4[row * 32 + cx] = make_float4(0.f, 0.f, 0.f, 0.f);
        }
    }
}

// Warp processes 8 edges: lanes 0-7 load metadata, shuffle-broadcast, then
// 8 overlapped 256B fp16 row loads (MLP=8) followed by 8 fp32 v4 reductions.
// NE % 8 == 0, grid sized exactly -> no bounds checks.
__global__ void k_edge(const int* __restrict__ src, const int* __restrict__ dst,
                       const float* __restrict__ wt) {
    int warp = (blockIdx.x * blockDim.x + threadIdx.x) >> 5;
    int lane = threadIdx.x & 31;
    int e0 = warp * 8;

    int s = 0, d = 0;
    float w = 0.f;
    if (lane < 8) {
        s = src[e0 + lane];
        d = dst[e0 + lane];
        w = wt[e0 + lane];
    }

    const uint2* z2 = (const uint2*)g_z;   // 4 halves per lane -> cols 4lane..4lane+3
    uint2 v[8];
#pragma unroll
    for (int i = 0; i < 8; i++) {
        int si = __shfl_sync(0xffffffffu, s, i);
        v[i] = z2[si * 32 + lane];
    }
#pragma unroll
    for (int i = 0; i < 8; i++) {
        int   di = __shfl_sync(0xffffffffu, d, i);
        float wi = __shfl_sync(0xffffffffu, w, i);
        float2 f0 = __half22float2(*(const __half2*)&v[i].x);
        float2 f1 = __half22float2(*(const __half2*)&v[i].y);
        float4* a = (float4*)g_agg + di * 32 + lane;
        asm volatile("red.global.add.v4.f32 [%0], {%1,%2,%3,%4};"
                     :: "l"(a), "f"(f0.x * wi), "f"(f0.y * wi),
                        "f"(f1.x * wi), "f"(f1.y * wi)
                     : "memory");
    }
}

// h2 = relu(agg2) + h1;  out = expmap0(h2): out[i,0]=cosh(n), out[i,1+c]=sinh(n)*h_c/n
__global__ void k_final(float* __restrict__ out) {
    int warp = (blockIdx.x * blockDim.x + threadIdx.x) >> 5;
    int lane = threadIdx.x & 31;
    if (warp >= N_NODES) return;
    float v[4];
    float n2 = 0.f;
#pragma unroll
    for (int j = 0; j < 4; j++) {
        int c = lane + 32 * j;
        float a  = g_agg[warp * DPAD + c];
        float hv = g_h[warp * DPAD + c];
        v[j] = (c < DS) ? (fmaxf(a, 0.f) + hv) : 0.f;
        n2 += v[j] * v[j];
    }
    n2 = warp_sum(n2);
    float n = fmaxf(sqrtf(n2), EPSF);
    float t = coshf(n);
    float f = sinhf(n) / n;
    if (lane == 0) out[warp * DPAD] = t;
#pragma unroll
    for (int j = 0; j < 4; j++) {
        int c = lane + 32 * j;
        if (c < DS) out[warp * DPAD + 1 + c] = f * v[j];
    }
}

extern "C" void kernel_launch(void* const* d_in, const int* in_sizes, int n_in,
                              void* d_out, int out_size) {
    const float* x  = (const float*)d_in[0];
    const float* W1 = (const float*)d_in[1];
    const float* b1 = (const float*)d_in[2];
    const float* W2 = (const float*)d_in[3];
    const float* b2 = (const float*)d_in[4];
    const int*   es = (const int*)d_in[5];
    const int*   ed = (const int*)d_in[6];
    const float* ew = (const float*)d_in[7];
    float* out = (float*)d_out;

    cudaFuncSetAttribute(k_gemm, cudaFuncAttributeMaxDynamicSharedMemorySize, SMEM_BYTES);

    int gemm_blocks = (N_NODES + GR - 1) / GR;       // 1563
    int edge_blocks = (NE / 8) / 8;                  // 12500 (8 warps/block, 8 edges/warp)
    int row_blocks  = (N_NODES * 32 + 255) / 256;    // 6250

    k_gemm<<<gemm_blocks, 256, SMEM_BYTES>>>(W1, b1, x, 0);
    k_edge<<<edge_blocks, 256>>>(es, ed, ew);

    k_gemm<<<gemm_blocks, 256, SMEM_BYTES>>>(W2, b2, x, 1);
    k_edge<<<edge_blocks, 256>>>(es, ed, ew);

    k_final<<<row_blocks, 256>>>(out);
}

// round 7
// speedup vs baseline: 1.5908x; 1.5908x over previous
#include <cuda_runtime.h>
#include <cuda_fp16.h>

#define N_NODES 50000
#define DS 127
#define DPAD 128
#define NE 800000
#define EPSF 1e-7f
#define GR 64   // rows per gemm block

// g_h  : h1 = relu(agg1)+x (fp32), written by layer-2 gemm prologue; pad col = 0
// g_z  : gemm output in fp16 (row stride 128 halves); pad col = 0
// g_agg: fp16 atomic accumulation target; pad col garbage, never read
__device__ __align__(16) float  g_h[N_NODES * DPAD];
__device__ __align__(16) __half g_z[N_NODES * DPAD];
__device__ __align__(16) __half g_agg[N_NODES * DPAD];

// smem floats: Wp[128*128 k-pair-interleaved] | h_s[64*128] | b_s[128] = 98816 B
#define H_OFF (DPAD * DPAD)
#define B_OFF (H_OFF + GR * DPAD)
#define SMEM_BYTES ((B_OFF + DPAD) * 4)

__device__ __forceinline__ float warp_sum(float v) {
#pragma unroll
    for (int o = 16; o; o >>= 1) v += __shfl_xor_sync(0xffffffffu, v, o);
    return v;
}

__device__ __forceinline__ void fma2(unsigned long long& acc,
                                     unsigned long long a, unsigned long long b) {
    asm("fma.rn.f32x2 %0, %1, %2, %0;" : "+l"(acc) : "l"(a), "l"(b));
}

extern __shared__ float smem[];

// z = half(h @ W + b); agg zeroed in epilogue.
// layer==0: h rows = x (logmap0(expmap0(x)) == x analytically).
// layer==1: h rows = relu(agg) + x (== h1), also stored to g_h for the final skip.
// 256 threads, 64 rows/block. Thread (cx=tid&31, ry=tid>>5): 8 rows x 4 cols.
// Accumulators are f32x2 {even-k, odd-k} partial sums per column; W stored in
// smem k-pair interleaved so one 64-bit lane operand = one column's k-pair.
__global__ void __launch_bounds__(256, 2)
k_gemm(const float* __restrict__ W, const float* __restrict__ b,
       const float* __restrict__ x, int layer) {
    float* Wp  = smem;
    float* h_s = smem + H_OFF;
    float* b_s = smem + B_OFF;
    int tid  = threadIdx.x;
    int row0 = blockIdx.x * GR;

    // Wp[(k>>1)*256 + c*2 + (k&1)] = W[k][c]; zeros for k==127 or c==127
    for (int i = tid; i < DPAD * DPAD; i += 256) {
        int k = i >> 7, c = i & 127;
        float v = (k < DS && c < DS) ? W[k * DS + c] : 0.f;
        Wp[(k >> 1) * 256 + c * 2 + (k & 1)] = v;
    }
    if (tid < DPAD) b_s[tid] = (tid < DS) ? b[tid] : 0.f;

    // h tile; pad col 127 -> 0
    {
        int c = tid & 127, rr = tid >> 7;
        const __half* aggh = g_agg;
        for (int r = rr; r < GR; r += 2) {
            int row = row0 + r;
            float v = 0.f;
            if (row < N_NODES) {
                if (c < DS) {
                    v = x[row * DS + c];
                    if (layer) {
                        v += fmaxf(__half2float(aggh[row * DPAD + c]), 0.f);
                        g_h[row * DPAD + c] = v;
                    }
                } else if (layer) {
                    g_h[row * DPAD + c] = 0.f;   // pad col of h1
                }
            }
            h_s[r * DPAD + c] = v;
        }
    }
    __syncthreads();

    int cx = tid & 31;
    int ry = tid >> 5;

    unsigned long long acc[8][4];
#pragma unroll
    for (int r = 0; r < 8; r++)
#pragma unroll
        for (int j = 0; j < 4; j++) acc[r][j] = 0ull;

    const ulonglong2*       Wu = (const ulonglong2*)Wp;        // 64 per k2 row
    const unsigned long long* Hu = (const unsigned long long*)h_s;  // 64 per h row

#pragma unroll 2
    for (int k2 = 0; k2 < 64; k2++) {
        ulonglong2 wA = Wu[k2 * 64 + 2 * cx];       // cols 4cx, 4cx+1
        ulonglong2 wB = Wu[k2 * 64 + 2 * cx + 1];   // cols 4cx+2, 4cx+3
#pragma unroll
        for (int r = 0; r < 8; r++) {
            unsigned long long h2 = Hu[(ry * 8 + r) * 64 + k2];  // broadcast {h2k, h2k+1}
            fma2(acc[r][0], h2, wA.x);
            fma2(acc[r][1], h2, wA.y);
            fma2(acc[r][2], h2, wB.x);
            fma2(acc[r][3], h2, wB.y);
        }
    }

    float4 bb = ((const float4*)b_s)[cx];
    uint2* z2 = (uint2*)g_z;     // 8B = 4 halves; 32 per row
    uint2* a2 = (uint2*)g_agg;
#pragma unroll
    for (int r = 0; r < 8; r++) {
        int row = row0 + ry * 8 + r;
        if (row < N_NODES) {
            float2 p0 = *(float2*)&acc[r][0];
            float2 p1 = *(float2*)&acc[r][1];
            float2 p2 = *(float2*)&acc[r][2];
            float2 p3 = *(float2*)&acc[r][3];
            __half2 h0 = __floats2half2_rn(p0.x + p0.y + bb.x, p1.x + p1.y + bb.y);
            __half2 h1 = __floats2half2_rn(p2.x + p2.y + bb.z, p3.x + p3.y + bb.w);
            uint2 o;
            o.x = *(unsigned*)&h0;
            o.y = *(unsigned*)&h1;
            z2[row * 32 + cx] = o;
            a2[row * 32 + cx] = make_uint2(0u, 0u);
        }
    }
}

// Warp processes 8 edges: lanes 0-7 load metadata, shuffle-broadcast, then
// 8 overlapped 256B fp16 row loads (MLP=8) followed by 8 fp16x2 v2 reductions.
// NE % 8 == 0, grid sized exactly -> no bounds checks.
__global__ void k_edge(const int* __restrict__ src, const int* __restrict__ dst,
                       const float* __restrict__ wt) {
    int warp = (blockIdx.x * blockDim.x + threadIdx.x) >> 5;
    int lane = threadIdx.x & 31;
    int e0 = warp * 8;

    int s = 0, d = 0;
    float w = 0.f;
    if (lane < 8) {
        s = src[e0 + lane];
        d = dst[e0 + lane];
        w = wt[e0 + lane];
    }

    const uint2* z2 = (const uint2*)g_z;   // 4 halves per lane -> cols 4lane..4lane+3
    uint2 v[8];
#pragma unroll
    for (int i = 0; i < 8; i++) {
        int si = __shfl_sync(0xffffffffu, s, i);
        v[i] = z2[si * 32 + lane];
    }
#pragma unroll
    for (int i = 0; i < 8; i++) {
        int   di = __shfl_sync(0xffffffffu, d, i);
        float wi = __shfl_sync(0xffffffffu, w, i);
        float2 f0 = __half22float2(*(const __half2*)&v[i].x);
        float2 f1 = __half22float2(*(const __half2*)&v[i].y);
        __half2 m0 = __floats2half2_rn(f0.x * wi, f0.y * wi);
        __half2 m1 = __floats2half2_rn(f1.x * wi, f1.y * wi);
        __half* a = g_agg + di * DPAD + 4 * lane;
        asm volatile("red.global.add.noftz.v2.f16x2 [%0], {%1,%2};"
                     :: "l"(a), "r"(*(unsigned*)&m0), "r"(*(unsigned*)&m1)
                     : "memory");
    }
}

// h2 = relu(agg2) + h1;  out = expmap0(h2): out[i,0]=cosh(n), out[i,1+c]=sinh(n)*h_c/n
__global__ void k_final(float* __restrict__ out) {
    int warp = (blockIdx.x * blockDim.x + threadIdx.x) >> 5;
    int lane = threadIdx.x & 31;
    if (warp >= N_NODES) return;
    float v[4];
    float n2 = 0.f;
#pragma unroll
    for (int j = 0; j < 4; j++) {
        int c = lane + 32 * j;
        float a  = __half2float(g_agg[warp * DPAD + c]);
        float hv = g_h[warp * DPAD + c];
        v[j] = (c < DS) ? (fmaxf(a, 0.f) + hv) : 0.f;
        n2 += v[j] * v[j];
    }
    n2 = warp_sum(n2);
    float n = fmaxf(sqrtf(n2), EPSF);
    float t = coshf(n);
    float f = sinhf(n) / n;
    if (lane == 0) out[warp * DPAD] = t;
#pragma unroll
    for (int j = 0; j < 4; j++) {
        int c = lane + 32 * j;
        if (c < DS) out[warp * DPAD + 1 + c] = f * v[j];
    }
}

extern "C" void kernel_launch(void* const* d_in, const int* in_sizes, int n_in,
                              void* d_out, int out_size) {
    const float* x  = (const float*)d_in[0];
    const float* W1 = (const float*)d_in[1];
    const float* b1 = (const float*)d_in[2];
    const float* W2 = (const float*)d_in[3];
    const float* b2 = (const float*)d_in[4];
    const int*   es = (const int*)d_in[5];
    const int*   ed = (const int*)d_in[6];
    const float* ew = (const float*)d_in[7];
    float* out = (float*)d_out;

    cudaFuncSetAttribute(k_gemm, cudaFuncAttributeMaxDynamicSharedMemorySize, SMEM_BYTES);

    int gemm_blocks = (N_NODES + GR - 1) / GR;       // 782
    int edge_blocks = (NE / 8) / 8;                  // 12500 (8 warps/block, 8 edges/warp)
    int row_blocks  = (N_NODES * 32 + 255) / 256;    // 6250

    k_gemm<<<gemm_blocks, 256, SMEM_BYTES>>>(W1, b1, x, 0);
    k_edge<<<edge_blocks, 256>>>(es, ed, ew);

    k_gemm<<<gemm_blocks, 256, SMEM_BYTES>>>(W2, b2, x, 1);
    k_edge<<<edge_blocks, 256>>>(es, ed, ew);

    k_final<<<row_blocks, 256>>>(out);
}

// round 8
// speedup vs baseline: 1.6217x; 1.0194x over previous
#include <cuda_runtime.h>
#include <cuda_fp16.h>

#define N_NODES 50000
#define DS 127
#define DPAD 128
#define NE 800000
#define EPSF 1e-7f
#define GR 64   // rows per gemm block

// g_h  : h1 = relu(agg1)+x (fp32), written by layer-2 gemm prologue; pad col = 0
// g_z  : gemm output in fp16 (row stride 128 halves); pad col = 0
// g_agg: fp16 atomic accumulation target; pad col garbage, never read
__device__ __align__(16) float  g_h[N_NODES * DPAD];
__device__ __align__(16) __half g_z[N_NODES * DPAD];
__device__ __align__(16) __half g_agg[N_NODES * DPAD];

// smem floats: WpA[8192] | WpB[8192] | h_s[64*128] | b_s[128] = 98816 B (2 CTAs/SM)
// WpA[k2*128 + lane*4 + sub*2 + par] = W[2*k2+par][4*lane+sub],     sub in {0,1}
// WpB[k2*128 + lane*4 + sub*2 + par] = W[2*k2+par][4*lane+2+sub],   sub in {0,1}
// => one 16B lane entry = two f32x2 col-pairs {evenK,oddK}; lane stride 16B (conflict-free)
#define WB_OFF 8192
#define H_OFF  16384
#define B_OFF  (H_OFF + GR * DPAD)
#define SMEM_BYTES ((B_OFF + DPAD) * 4)

__device__ __forceinline__ float warp_sum(float v) {
#pragma unroll
    for (int o = 16; o; o >>= 1) v += __shfl_xor_sync(0xffffffffu, v, o);
    return v;
}

__device__ __forceinline__ void fma2(unsigned long long& acc,
                                     unsigned long long a, unsigned long long b) {
    asm("fma.rn.f32x2 %0, %1, %2, %0;" : "+l"(acc) : "l"(a), "l"(b));
}

extern __shared__ float smem[];

// z = half(h @ W + b); agg zeroed in epilogue.
// layer==0: h rows = x (logmap0(expmap0(x)) == x analytically).
// layer==1: h rows = relu(agg) + x (== h1), also stored to g_h for the final skip.
// 256 threads, 64 rows/block. Thread (cx=tid&31, ry=tid>>5): 8 rows x 4 cols.
// Accumulators f32x2 {even-k, odd-k} partial sums per column, halves added at end.
__global__ void __launch_bounds__(256, 2)
k_gemm(const float* __restrict__ W, const float* __restrict__ b,
       const float* __restrict__ x, int layer) {
    float* WpA = smem;
    float* WpB = smem + WB_OFF;
    float* h_s = smem + H_OFF;
    float* b_s = smem + B_OFF;
    int tid  = threadIdx.x;
    int row0 = blockIdx.x * GR;

    // W fill into split k-pair layout; zeros for k==127 or c==127
    for (int i = tid; i < DPAD * DPAD; i += 256) {
        int k = i >> 7, c = i & 127;
        float v = (k < DS && c < DS) ? W[k * DS + c] : 0.f;
        int k2 = k >> 1, par = k & 1, lane = c >> 2, sub = c & 3;
        float* dstp = (sub < 2) ? WpA : WpB;
        dstp[k2 * 128 + lane * 4 + (sub & 1) * 2 + par] = v;
    }
    if (tid < DPAD) b_s[tid] = (tid < DS) ? b[tid] : 0.f;

    // h tile; pad col 127 -> 0
    {
        int c = tid & 127, rr = tid >> 7;
        const __half* aggh = g_agg;
        for (int r = rr; r < GR; r += 2) {
            int row = row0 + r;
            float v = 0.f;
            if (row < N_NODES) {
                if (c < DS) {
                    v = x[row * DS + c];
                    if (layer) {
                        v += fmaxf(__half2float(aggh[row * DPAD + c]), 0.f);
                        g_h[row * DPAD + c] = v;
                    }
                } else if (layer) {
                    g_h[row * DPAD + c] = 0.f;   // pad col of h1
                }
            }
            h_s[r * DPAD + c] = v;
        }
    }
    __syncthreads();

    int cx = tid & 31;
    int ry = tid >> 5;

    unsigned long long acc[8][4];
#pragma unroll
    for (int r = 0; r < 8; r++)
#pragma unroll
        for (int j = 0; j < 4; j++) acc[r][j] = 0ull;

    const ulonglong2* WA  = (const ulonglong2*)WpA;   // [k2*32 + cx]
    const ulonglong2* WB  = (const ulonglong2*)WpB;   // [k2*32 + cx]
    const ulonglong2* H16 = (const ulonglong2*)h_s;   // [row*32 + kk] = {h4kk..h4kk+3}

#pragma unroll 2
    for (int kk = 0; kk < 32; kk++) {   // kk = k2/2; covers k = 4kk .. 4kk+3
        ulonglong2 wA0 = WA[(2 * kk)     * 32 + cx];
        ulonglong2 wB0 = WB[(2 * kk)     * 32 + cx];
        ulonglong2 wA1 = WA[(2 * kk + 1) * 32 + cx];
        ulonglong2 wB1 = WB[(2 * kk + 1) * 32 + cx];
#pragma unroll
        for (int r = 0; r < 8; r++) {
            ulonglong2 h = H16[(ry * 8 + r) * 32 + kk];  // broadcast, 16B
            fma2(acc[r][0], h.x, wA0.x);
            fma2(acc[r][1], h.x, wA0.y);
            fma2(acc[r][2], h.x, wB0.x);
            fma2(acc[r][3], h.x, wB0.y);
            fma2(acc[r][0], h.y, wA1.x);
            fma2(acc[r][1], h.y, wA1.y);
            fma2(acc[r][2], h.y, wB1.x);
            fma2(acc[r][3], h.y, wB1.y);
        }
    }

    float4 bb = ((const float4*)b_s)[cx];
    uint2* z2 = (uint2*)g_z;     // 8B = 4 halves; 32 per row
    uint2* a2 = (uint2*)g_agg;
#pragma unroll
    for (int r = 0; r < 8; r++) {
        int row = row0 + ry * 8 + r;
        if (row < N_NODES) {
            float2 p0 = *(float2*)&acc[r][0];
            float2 p1 = *(float2*)&acc[r][1];
            float2 p2 = *(float2*)&acc[r][2];
            float2 p3 = *(float2*)&acc[r][3];
            __half2 h0 = __floats2half2_rn(p0.x + p0.y + bb.x, p1.x + p1.y + bb.y);
            __half2 h1 = __floats2half2_rn(p2.x + p2.y + bb.z, p3.x + p3.y + bb.w);
            uint2 o;
            o.x = *(unsigned*)&h0;
            o.y = *(unsigned*)&h1;
            z2[row * 32 + cx] = o;
            a2[row * 32 + cx] = make_uint2(0u, 0u);
        }
    }
}

// Warp processes 8 edges: lanes 0-7 load metadata, shuffle-broadcast, then
// 8 overlapped 256B fp16 row loads (MLP=8) followed by 8 fp16x2 v2 reductions.
// NE % 8 == 0, grid sized exactly -> no bounds checks.
__global__ void k_edge(const int* __restrict__ src, const int* __restrict__ dst,
                       const float* __restrict__ wt) {
    int warp = (blockIdx.x * blockDim.x + threadIdx.x) >> 5;
    int lane = threadIdx.x & 31;
    int e0 = warp * 8;

    int s = 0, d = 0;
    float w = 0.f;
    if (lane < 8) {
        s = src[e0 + lane];
        d = dst[e0 + lane];
        w = wt[e0 + lane];
    }

    const uint2* z2 = (const uint2*)g_z;   // 4 halves per lane -> cols 4lane..4lane+3
    uint2 v[8];
#pragma unroll
    for (int i = 0; i < 8; i++) {
        int si = __shfl_sync(0xffffffffu, s, i);
        v[i] = z2[si * 32 + lane];
    }
#pragma unroll
    for (int i = 0; i < 8; i++) {
        int   di = __shfl_sync(0xffffffffu, d, i);
        float wi = __shfl_sync(0xffffffffu, w, i);
        float2 f0 = __half22float2(*(const __half2*)&v[i].x);
        float2 f1 = __half22float2(*(const __half2*)&v[i].y);
        __half2 m0 = __floats2half2_rn(f0.x * wi, f0.y * wi);
        __half2 m1 = __floats2half2_rn(f1.x * wi, f1.y * wi);
        __half* a = g_agg + di * DPAD + 4 * lane;
        asm volatile("red.global.add.noftz.v2.f16x2 [%0], {%1,%2};"
                     :: "l"(a), "r"(*(unsigned*)&m0), "r"(*(unsigned*)&m1)
                     : "memory");
    }
}

// h2 = relu(agg2) + h1;  out = expmap0(h2): out[i,0]=cosh(n), out[i,1+c]=sinh(n)*h_c/n
__global__ void k_final(float* __restrict__ out) {
    int warp = (blockIdx.x * blockDim.x + threadIdx.x) >> 5;
    int lane = threadIdx.x & 31;
    if (warp >= N_NODES) return;
    float v[4];
    float n2 = 0.f;
#pragma unroll
    for (int j = 0; j < 4; j++) {
        int c = lane + 32 * j;
        float a  = __half2float(g_agg[warp * DPAD + c]);
        float hv = g_h[warp * DPAD + c];
        v[j] = (c < DS) ? (fmaxf(a, 0.f) + hv) : 0.f;
        n2 += v[j] * v[j];
    }
    n2 = warp_sum(n2);
    float n = fmaxf(sqrtf(n2), EPSF);
    float t = coshf(n);
    float f = sinhf(n) / n;
    if (lane == 0) out[warp * DPAD] = t;
#pragma unroll
    for (int j = 0; j < 4; j++) {
        int c = lane + 32 * j;
        if (c < DS) out[warp * DPAD + 1 + c] = f * v[j];
    }
}

extern "C" void kernel_launch(void* const* d_in, const int* in_sizes, int n_in,
                              void* d_out, int out_size) {
    const float* x  = (const float*)d_in[0];
    const float* W1 = (const float*)d_in[1];
    const float* b1 = (const float*)d_in[2];
    const float* W2 = (const float*)d_in[3];
    const float* b2 = (const float*)d_in[4];
    const int*   es = (const int*)d_in[5];
    const int*   ed = (const int*)d_in[6];
    const float* ew = (const float*)d_in[7];
    float* out = (float*)d_out;

    cudaFuncSetAttribute(k_gemm, cudaFuncAttributeMaxDynamicSharedMemorySize, SMEM_BYTES);

    int gemm_blocks = (N_NODES + GR - 1) / GR;       // 782
    int edge_blocks = (NE / 8) / 8;                  // 12500 (8 warps/block, 8 edges/warp)
    int row_blocks  = (N_NODES * 32 + 255) / 256;    // 6250

    k_gemm<<<gemm_blocks, 256, SMEM_BYTES>>>(W1, b1, x, 0);
    k_edge<<<edge_blocks, 256>>>(es, ed, ew);

    k_gemm<<<gemm_blocks, 256, SMEM_BYTES>>>(W2, b2, x, 1);
    k_edge<<<edge_blocks, 256>>>(es, ed, ew);

    k_final<<<row_blocks, 256>>>(out);
}